// round 1
// baseline (speedup 1.0000x reference)
#include <cuda_runtime.h>
#include <math.h>

#define H 1024
#define B 256
#define T 256
#define C 10

// Persistent state (allocation-free scratch): ping-pong h, in-place c.
__device__ float g_h[2][H * B];
__device__ float g_c[H * B];

__global__ void lstm_init_kernel() {
    int i = blockIdx.x * blockDim.x + threadIdx.x;
    if (i < H * B) {
        g_h[0][i] = 0.0f;
        g_c[i] = 0.0f;
    }
}

// One timestep: all 4 gate GEMMs + LSTM pointwise update, fused.
// Grid: (H/32, B/64) = (32, 4) = 128 CTAs, 256 threads.
// Thread micro-tile: 4 gates x 2 rows x 4 cols.
__global__ void __launch_bounds__(256) lstm_step_kernel(
    const float* __restrict__ x,
    const float* __restrict__ Wgx, const float* __restrict__ Wgh,
    const float* __restrict__ Wix, const float* __restrict__ Wih,
    const float* __restrict__ Wfx, const float* __restrict__ Wfh,
    const float* __restrict__ Wox, const float* __restrict__ Woh,
    const float* __restrict__ bg,  const float* __restrict__ bi,
    const float* __restrict__ bfv, const float* __restrict__ bo,
    int t)
{
    const float* __restrict__ h_in = g_h[t & 1];
    float* __restrict__ h_out = g_h[(t + 1) & 1];

    __shared__ float hs[16][64];        // h tile: [k][b]
    __shared__ float Ws[4][16][33];     // W tiles, k-major: [gate][k][i], padded

    const int tid = threadIdx.x;
    const int i0 = blockIdx.x * 32;     // H-row tile base
    const int b0 = blockIdx.y * 64;     // B-col tile base

    const int tr = tid >> 4;            // 0..15 -> rows tr*2, tr*2+1
    const int tc = tid & 15;            // 0..15 -> cols tc*4 .. tc*4+3

    float acc[4][2][4];
#pragma unroll
    for (int g = 0; g < 4; g++)
#pragma unroll
        for (int r = 0; r < 2; r++)
#pragma unroll
            for (int j = 0; j < 4; j++)
                acc[g][r][j] = 0.0f;

    const float* __restrict__ Wh[4] = {Wgh, Wih, Wfh, Woh};

    // h-tile load indices: 16 rows x 64 cols, 4 floats/thread
    const int hr = tid >> 4;            // row 0..15
    const int hc = (tid & 15) * 4;      // col base
    // W-tile load indices: 32 rows(i) x 16 cols(k), float2/thread/gate
    const int wr = tid >> 3;            // i 0..31
    const int wk = (tid & 7) * 2;       // k base

    for (int k0 = 0; k0 < H; k0 += 16) {
        // Load h tile (coalesced 256B rows)
        float4 hv = *(const float4*)&h_in[(k0 + hr) * B + b0 + hc];
        *(float4*)&hs[hr][hc] = hv;
        // Load 4 W tiles, transpose to k-major in smem
#pragma unroll
        for (int g = 0; g < 4; g++) {
            float2 wv = *(const float2*)&Wh[g][(i0 + wr) * H + k0 + wk];
            Ws[g][wk][wr] = wv.x;
            Ws[g][wk + 1][wr] = wv.y;
        }
        __syncthreads();

#pragma unroll
        for (int kk = 0; kk < 16; kk++) {
            float bv[4];
            *(float4*)bv = *(const float4*)&hs[kk][tc * 4];
#pragma unroll
            for (int g = 0; g < 4; g++) {
                float a0 = Ws[g][kk][tr * 2];
                float a1 = Ws[g][kk][tr * 2 + 1];
#pragma unroll
                for (int j = 0; j < 4; j++) {
                    acc[g][0][j] = fmaf(a0, bv[j], acc[g][0][j]);
                    acc[g][1][j] = fmaf(a1, bv[j], acc[g][1][j]);
                }
            }
        }
        __syncthreads();
    }

    // Epilogue: x-outer-product term + bias + nonlinearities + c/h update
    float xv[4], bgv[4], biv[4], bfvv[4], bov[4];
#pragma unroll
    for (int j = 0; j < 4; j++) {
        int b = b0 + tc * 4 + j;
        xv[j]   = x[b * T + t];
        bgv[j]  = bg[b];
        biv[j]  = bi[b];
        bfvv[j] = bfv[b];
        bov[j]  = bo[b];
    }
#pragma unroll
    for (int r = 0; r < 2; r++) {
        int i = i0 + tr * 2 + r;
        float wgx = Wgx[i], wix = Wix[i], wfx = Wfx[i], wox = Wox[i];
#pragma unroll
        for (int j = 0; j < 4; j++) {
            int b = b0 + tc * 4 + j;
            float pg = acc[0][r][j] + wgx * xv[j] + bgv[j];
            float pi = acc[1][r][j] + wix * xv[j] + biv[j];
            float pf = acc[2][r][j] + wfx * xv[j] + bfvv[j];
            float po = acc[3][r][j] + wox * xv[j] + bov[j];

            float gg = tanhf(pg);
            float ii = 1.0f / (1.0f + expf(-pi));
            float ff = 1.0f / (1.0f + expf(-pf));
            float oo = 1.0f / (1.0f + expf(-po));

            int idx = i * B + b;
            float c_new = gg * ii + g_c[idx] * ff;
            g_c[idx] = c_new;
            h_out[idx] = tanhf(c_new) * oo;
        }
    }
}

// p = W_ph @ h_T + b_p ; softmax over axis=1 (batch dim); out = y.T (B x C)
__global__ void __launch_bounds__(256) proj_softmax_kernel(
    const float* __restrict__ Wph, const float* __restrict__ bp,
    float* __restrict__ out)
{
    const float* __restrict__ hT = g_h[0];  // after even number of steps
    const int b = threadIdx.x;

    float p[C];
#pragma unroll
    for (int c = 0; c < C; c++) p[c] = 0.0f;

    for (int k = 0; k < H; k++) {
        float hv = hT[k * B + b];   // coalesced across threads
#pragma unroll
        for (int c = 0; c < C; c++)
            p[c] = fmaf(Wph[c * H + k], hv, p[c]);  // broadcast load
    }
    float bpb = bp[b];
#pragma unroll
    for (int c = 0; c < C; c++) p[c] += bpb;

    __shared__ float red[256];
    for (int c = 0; c < C; c++) {
        // max over batch dim
        red[b] = p[c];
        __syncthreads();
        for (int s = 128; s > 0; s >>= 1) {
            if (b < s) red[b] = fmaxf(red[b], red[b + s]);
            __syncthreads();
        }
        float m = red[0];
        __syncthreads();
        float e = expf(p[c] - m);
        red[b] = e;
        __syncthreads();
        for (int s = 128; s > 0; s >>= 1) {
            if (b < s) red[b] += red[b + s];
            __syncthreads();
        }
        float ssum = red[0];
        __syncthreads();
        out[b * C + c] = e / ssum;
    }
}

extern "C" void kernel_launch(void* const* d_in, const int* in_sizes, int n_in,
                              void* d_out, int out_size) {
    const float* x   = (const float*)d_in[0];
    const float* Wgx = (const float*)d_in[1];
    const float* Wgh = (const float*)d_in[2];
    const float* Wix = (const float*)d_in[3];
    const float* Wih = (const float*)d_in[4];
    const float* Wfx = (const float*)d_in[5];
    const float* Wfh = (const float*)d_in[6];
    const float* Wox = (const float*)d_in[7];
    const float* Woh = (const float*)d_in[8];
    const float* Wph = (const float*)d_in[9];
    const float* bg  = (const float*)d_in[10];
    const float* bi  = (const float*)d_in[11];
    const float* bfv = (const float*)d_in[12];
    const float* bo  = (const float*)d_in[13];
    const float* bp  = (const float*)d_in[14];
    float* out = (float*)d_out;

    lstm_init_kernel<<<(H * B + 255) / 256, 256>>>();

    dim3 grid(H / 32, B / 64);  // 32 x 4 = 128 CTAs
    for (int t = 0; t < T; t++) {
        lstm_step_kernel<<<grid, 256>>>(x, Wgx, Wgh, Wix, Wih, Wfx, Wfh,
                                        Wox, Woh, bg, bi, bfv, bo, t);
    }
    proj_softmax_kernel<<<1, 256>>>(Wph, bp, out);
}

// round 5
// speedup vs baseline: 1.0414x; 1.0414x over previous
#include <cuda_runtime.h>
#include <math.h>

#define H 1024
#define B 256
#define T 256
#define C 10
#define KT 16

// Persistent state (allocation-free scratch): ping-pong h, in-place c.
__device__ float g_h[2][H * B];
__device__ float g_c[H * B];

__global__ void lstm_init_kernel() {
    int i = blockIdx.x * blockDim.x + threadIdx.x;
    if (i < H * B) {
        g_h[0][i] = 0.0f;
        g_c[i] = 0.0f;
    }
}

__device__ __forceinline__ unsigned long long dup2(float w) {
    unsigned long long r;
    asm("mov.b64 %0, {%1, %1};" : "=l"(r) : "f"(w));
    return r;
}
__device__ __forceinline__ void ffma2(unsigned long long& d,
                                      unsigned long long a,
                                      unsigned long long b) {
    asm("fma.rn.f32x2 %0, %1, %2, %0;" : "+l"(d) : "l"(a), "l"(b));
}
__device__ __forceinline__ float2 unpack2(unsigned long long v) {
    float2 f;
    asm("mov.b64 {%0, %1}, %2;" : "=f"(f.x), "=f"(f.y) : "l"(v));
    return f;
}

// One timestep: 4 gate GEMMs (4096x256x1024 total) + LSTM pointwise update.
// Grid: (H/32, B/64) = (32, 4) = 128 CTAs, 256 threads.
// Thread micro-tile: 4 gates x 2 i-rows x 4 b-cols (as 2 f32x2 accumulators each).
__global__ void __launch_bounds__(256) lstm_step_kernel(
    const float* __restrict__ x,
    const float* __restrict__ Wgx, const float* __restrict__ Wgh,
    const float* __restrict__ Wix, const float* __restrict__ Wih,
    const float* __restrict__ Wfx, const float* __restrict__ Wfh,
    const float* __restrict__ Wox, const float* __restrict__ Woh,
    const float* __restrict__ bg,  const float* __restrict__ bi,
    const float* __restrict__ bfv, const float* __restrict__ bo,
    int t)
{
    const float* __restrict__ h_in = g_h[t & 1];
    float* __restrict__ h_out = g_h[(t + 1) & 1];

    __shared__ float hs[KT][64];                         // h tile [k][b]
    __shared__ unsigned long long Ws2[KT][32][4];        // W dup-pairs [k][i][gate^((k>>2)&3)]

    const int tid = threadIdx.x;
    const int i0 = blockIdx.x * 32;
    const int b0 = blockIdx.y * 64;

    const int tr = tid >> 4;            // 0..15 -> i rows tr*2, tr*2+1
    const int tc = tid & 15;            // 0..15 -> b cols tc*4..tc*4+3

    // ---- load-index decode ----
    // h tile: 16 rows x 64 cols, one float4 per thread
    const int hr = tid >> 4;
    const int hc = (tid & 15) * 4;
    // W tiles: per round r in {0,1}: gate = (tid>>7) + 2r, i = (tid>>2)&31, kc = tid&3
    const int wkc = tid & 3;
    const int wi  = (tid >> 2) & 31;
    const int wgb = tid >> 7;           // 0 or 1

    const float* __restrict__ Wp0 = wgb ? Wih : Wgh;    // round 0: gates 0,1
    const float* __restrict__ Wp1 = wgb ? Woh : Wfh;    // round 1: gates 2,3

    const float* pH  = h_in + hr * B + b0 + hc;
    const float* pW0 = Wp0 + (i0 + wi) * H + wkc * 4;
    const float* pW1 = Wp1 + (i0 + wi) * H + wkc * 4;

    unsigned long long acc[4][2][2];
#pragma unroll
    for (int g = 0; g < 4; g++)
#pragma unroll
        for (int r = 0; r < 2; r++)
#pragma unroll
            for (int p = 0; p < 2; p++)
                acc[g][r][p] = 0ull;

    // prefetch tile 0
    float4 hv  = *(const float4*)pH;
    float4 wv0 = *(const float4*)pW0;
    float4 wv1 = *(const float4*)pW1;

    for (int k0 = 0; k0 < H; k0 += KT) {
        // ---- store staged tile to smem ----
        *(float4*)&hs[hr][hc] = hv;
        {
            const int g0 = wgb;          // round 0 gate
            const int g1 = 2 + wgb;      // round 1 gate
            const int s0 = g0 ^ wkc;     // swizzled slot
            const int s1 = g1 ^ wkc;
            Ws2[wkc * 4 + 0][wi][s0] = dup2(wv0.x);
            Ws2[wkc * 4 + 1][wi][s0] = dup2(wv0.y);
            Ws2[wkc * 4 + 2][wi][s0] = dup2(wv0.z);
            Ws2[wkc * 4 + 3][wi][s0] = dup2(wv0.w);
            Ws2[wkc * 4 + 0][wi][s1] = dup2(wv1.x);
            Ws2[wkc * 4 + 1][wi][s1] = dup2(wv1.y);
            Ws2[wkc * 4 + 2][wi][s1] = dup2(wv1.z);
            Ws2[wkc * 4 + 3][wi][s1] = dup2(wv1.w);
        }
        __syncthreads();

        // ---- prefetch next tile ----
        if (k0 + KT < H) {
            pH += KT * B;
            pW0 += KT;
            pW1 += KT;
            hv  = *(const float4*)pH;
            wv0 = *(const float4*)pW0;
            wv1 = *(const float4*)pW1;
        }

        // ---- compute ----
#pragma unroll
        for (int kk = 0; kk < KT; kk++) {
            const int sw = (kk >> 2) & 3;
            const ulonglong2 ha = *(const ulonglong2*)&hs[kk][tc * 4];
            const ulonglong2 wa01 = *(const ulonglong2*)&Ws2[kk][tr * 2][0];
            const ulonglong2 wa23 = *(const ulonglong2*)&Ws2[kk][tr * 2][2];
            const ulonglong2 wb01 = *(const ulonglong2*)&Ws2[kk][tr * 2 + 1][0];
            const ulonglong2 wb23 = *(const ulonglong2*)&Ws2[kk][tr * 2 + 1][2];
            const unsigned long long sa[4] = {wa01.x, wa01.y, wa23.x, wa23.y};
            const unsigned long long sb[4] = {wb01.x, wb01.y, wb23.x, wb23.y};
#pragma unroll
            for (int g = 0; g < 4; g++) {
                const unsigned long long wga = sa[g ^ sw];
                const unsigned long long wgb2 = sb[g ^ sw];
                ffma2(acc[g][0][0], wga, ha.x);
                ffma2(acc[g][0][1], wga, ha.y);
                ffma2(acc[g][1][0], wgb2, ha.x);
                ffma2(acc[g][1][1], wgb2, ha.y);
            }
        }
        __syncthreads();
    }

    // ---- epilogue: x outer-product + bias + nonlinearities + c/h update ----
    float xv[4], bgv[4], biv[4], bfvv[4], bov[4];
#pragma unroll
    for (int j = 0; j < 4; j++) {
        int b = b0 + tc * 4 + j;
        xv[j]   = x[b * T + t];
        bgv[j]  = bg[b];
        biv[j]  = bi[b];
        bfvv[j] = bfv[b];
        bov[j]  = bo[b];
    }
#pragma unroll
    for (int r = 0; r < 2; r++) {
        const int i = i0 + tr * 2 + r;
        const float wgx = Wgx[i], wix = Wix[i], wfx = Wfx[i], wox = Wox[i];
        float accf[4][4];
#pragma unroll
        for (int g = 0; g < 4; g++) {
            float2 lo = unpack2(acc[g][r][0]);
            float2 hi2 = unpack2(acc[g][r][1]);
            accf[g][0] = lo.x; accf[g][1] = lo.y;
            accf[g][2] = hi2.x; accf[g][3] = hi2.y;
        }
#pragma unroll
        for (int j = 0; j < 4; j++) {
            const int b = b0 + tc * 4 + j;
            const float pg = accf[0][j] + wgx * xv[j] + bgv[j];
            const float pi = accf[1][j] + wix * xv[j] + biv[j];
            const float pf = accf[2][j] + wfx * xv[j] + bfvv[j];
            const float po = accf[3][j] + wox * xv[j] + bov[j];

            const float gg = tanhf(pg);
            const float ii = 1.0f / (1.0f + expf(-pi));
            const float ff = 1.0f / (1.0f + expf(-pf));
            const float oo = 1.0f / (1.0f + expf(-po));

            const int idx = i * B + b;
            const float c_new = gg * ii + g_c[idx] * ff;
            g_c[idx] = c_new;
            h_out[idx] = tanhf(c_new) * oo;
        }
    }
}

// p = W_ph @ h_T + b_p ; softmax over axis=1 (batch dim); out = y.T (B x C)
__global__ void __launch_bounds__(256) proj_softmax_kernel(
    const float* __restrict__ Wph, const float* __restrict__ bp,
    float* __restrict__ out)
{
    const float* __restrict__ hT = g_h[0];  // after even number of steps
    const int b = threadIdx.x;

    float p[C];
#pragma unroll
    for (int c = 0; c < C; c++) p[c] = 0.0f;

    for (int k = 0; k < H; k++) {
        float hv = hT[k * B + b];
#pragma unroll
        for (int c = 0; c < C; c++)
            p[c] = fmaf(Wph[c * H + k], hv, p[c]);
    }
    float bpb = bp[b];
#pragma unroll
    for (int c = 0; c < C; c++) p[c] += bpb;

    __shared__ float red[256];
    for (int c = 0; c < C; c++) {
        red[b] = p[c];
        __syncthreads();
        for (int s = 128; s > 0; s >>= 1) {
            if (b < s) red[b] = fmaxf(red[b], red[b + s]);
            __syncthreads();
        }
        float m = red[0];
        __syncthreads();
        float e = expf(p[c] - m);
        red[b] = e;
        __syncthreads();
        for (int s = 128; s > 0; s >>= 1) {
            if (b < s) red[b] += red[b + s];
            __syncthreads();
        }
        float ssum = red[0];
        __syncthreads();
        out[b * C + c] = e / ssum;
    }
}

extern "C" void kernel_launch(void* const* d_in, const int* in_sizes, int n_in,
                              void* d_out, int out_size) {
    const float* x   = (const float*)d_in[0];
    const float* Wgx = (const float*)d_in[1];
    const float* Wgh = (const float*)d_in[2];
    const float* Wix = (const float*)d_in[3];
    const float* Wih = (const float*)d_in[4];
    const float* Wfx = (const float*)d_in[5];
    const float* Wfh = (const float*)d_in[6];
    const float* Wox = (const float*)d_in[7];
    const float* Woh = (const float*)d_in[8];
    const float* Wph = (const float*)d_in[9];
    const float* bg  = (const float*)d_in[10];
    const float* bi  = (const float*)d_in[11];
    const float* bfv = (const float*)d_in[12];
    const float* bo  = (const float*)d_in[13];
    const float* bp  = (const float*)d_in[14];
    float* out = (float*)d_out;

    lstm_init_kernel<<<(H * B + 255) / 256, 256>>>();

    dim3 grid(H / 32, B / 64);  // 128 CTAs
    for (int t = 0; t < T; t++) {
        lstm_step_kernel<<<grid, 256>>>(x, Wgx, Wgh, Wix, Wih, Wfx, Wfh,
                                        Wox, Woh, bg, bi, bfv, bo, t);
    }
    proj_softmax_kernel<<<1, 256>>>(Wph, bp, out);
}

// round 7
// speedup vs baseline: 2.5116x; 2.4118x over previous
#include <cuda_runtime.h>
#include <cuda_bf16.h>
#include <math.h>
#include <stdint.h>

#define H 1024
#define B 256
#define T 256
#define C 10

#define M_TILE 128
#define N_TILE 64
#define KC 64
#define NCHUNK 16            // 1024 / 64
#define N_THREADS 256

// smem tile geometry: rows padded to 72 halves (144B) for conflict-free ldmatrix
#define ROW_BYTES 144
#define A_PLANE_BYTES (M_TILE * ROW_BYTES)      // 18432
#define B_PLANE_BYTES (N_TILE * ROW_BYTES)      // 9216
#define OFF_AH 0
#define OFF_AL A_PLANE_BYTES
#define OFF_BH (2 * A_PLANE_BYTES)
#define OFF_BL (2 * A_PLANE_BYTES + B_PLANE_BYTES)
#define STAGE_BYTES (2 * A_PLANE_BYTES + 2 * B_PLANE_BYTES)   // 55296
#define SMEM_TOTAL (2 * STAGE_BYTES)                          // 110592
#define EP_STRIDE 65          // fp32 epilogue tile stride (conflict-free columns)

// ---- persistent device state (no allocation) ----
__device__ __nv_bfloat16 g_pw[2][4096][1024];   // packed W planes [hi/lo][m][k]
__device__ float         g_pwx[4096];           // packed x-weights (same row perm)
__device__ __nv_bfloat16 g_hbf[2][2][B][H];     // [pingpong][plane][b][i]
__device__ float         g_c[B * H];            // cell state [b][i]
__device__ float         g_h32[B * H];          // fp32 h for projection [b][i]

// ---------------- helpers ----------------
__device__ __forceinline__ uint32_t smem_u32(const void* p) {
    uint32_t a;
    asm("{ .reg .u64 t; cvta.to.shared.u64 t, %1; cvt.u32.u64 %0, t; }" : "=r"(a) : "l"(p));
    return a;
}
#define CP_ASYNC16(dst, src) asm volatile("cp.async.cg.shared.global [%0], [%1], 16;" :: "r"(dst), "l"(src) : "memory")
#define CP_COMMIT() asm volatile("cp.async.commit_group;" ::: "memory")
#define CP_WAIT(n)  asm volatile("cp.async.wait_group %0;" :: "n"(n) : "memory")

__device__ __forceinline__ void ldsm_x4(uint32_t* r, uint32_t addr) {
    asm volatile("ldmatrix.sync.aligned.m8n8.x4.shared.b16 {%0,%1,%2,%3}, [%4];"
        : "=r"(r[0]), "=r"(r[1]), "=r"(r[2]), "=r"(r[3]) : "r"(addr));
}
__device__ __forceinline__ void mma_bf16(float* d, const uint32_t* a,
                                         uint32_t b0, uint32_t b1) {
    asm volatile("mma.sync.aligned.m16n8k16.row.col.f32.bf16.bf16.f32 "
        "{%0,%1,%2,%3}, {%4,%5,%6,%7}, {%8,%9}, {%0,%1,%2,%3};"
        : "+f"(d[0]), "+f"(d[1]), "+f"(d[2]), "+f"(d[3])
        : "r"(a[0]), "r"(a[1]), "r"(a[2]), "r"(a[3]), "r"(b0), "r"(b1));
}
__device__ __forceinline__ float sigm(float v) { return 1.0f / (1.0f + __expf(-v)); }
__device__ __forceinline__ float tanh_fast(float v) { return 2.0f * sigm(2.0f * v) - 1.0f; }

// ---------------- pack / init ----------------
__global__ void pack_w_kernel(const float* __restrict__ Wgh, const float* __restrict__ Wih,
                              const float* __restrict__ Wfh, const float* __restrict__ Woh) {
    int idx = blockIdx.x * 256 + threadIdx.x;           // 4M
    int gate = idx >> 20;
    int rem = idx & 0xFFFFF;
    int i = rem >> 10;
    int k = rem & 1023;
    const float* W = (gate == 0) ? Wgh : (gate == 1) ? Wih : (gate == 2) ? Wfh : Woh;
    float w = W[i * H + k];
    __nv_bfloat16 hi = __float2bfloat16(w);
    float lo = w - __bfloat162float(hi);
    int m = ((i >> 5) << 7) + (gate << 5) + (i & 31);   // gate-interleaved rows
    g_pw[0][m][k] = hi;
    g_pw[1][m][k] = __float2bfloat16(lo);
}

__global__ void pack_wx_kernel(const float* __restrict__ Wgx, const float* __restrict__ Wix,
                               const float* __restrict__ Wfx, const float* __restrict__ Wox) {
    int idx = blockIdx.x * 256 + threadIdx.x;           // 4096
    int gate = idx >> 10;
    int i = idx & 1023;
    const float* W = (gate == 0) ? Wgx : (gate == 1) ? Wix : (gate == 2) ? Wfx : Wox;
    int m = ((i >> 5) << 7) + (gate << 5) + (i & 31);
    g_pwx[m] = W[i];
}

__global__ void lstm_init_kernel() {
    int idx = blockIdx.x * 256 + threadIdx.x;           // 524288
    if (idx < 262144) {
        ((uint32_t*)&g_hbf[0][0][0][0])[idx] = 0;       // zero pp0 hi+lo planes
    } else {
        g_c[idx - 262144] = 0.0f;
    }
}

// ---------------- one timestep ----------------
// grid (32, 4): mt = 4-gate x 32-row block of packed W, nt = 64-batch block.
__global__ void __launch_bounds__(N_THREADS, 1) lstm_step_kernel(
    const float* __restrict__ x,
    const float* __restrict__ bg, const float* __restrict__ bi,
    const float* __restrict__ bf, const float* __restrict__ bo,
    int t)
{
    extern __shared__ char smem[];
    const uint32_t sb = smem_u32(smem);
    const int tid = threadIdx.x;
    const int lane = tid & 31;
    const int wid = tid >> 5;
    const int warp_m = wid & 3;         // 4 m-warps x 32 rows
    const int warp_n = wid >> 2;        // 2 n-warps x 32 cols
    const int mt = blockIdx.x;
    const int nt = blockIdx.y;
    const int pp = t & 1;

    const __nv_bfloat16* srcAh = &g_pw[0][mt * M_TILE][0];
    const __nv_bfloat16* srcAl = &g_pw[1][mt * M_TILE][0];
    const __nv_bfloat16* srcBh = &g_hbf[pp][0][nt * N_TILE][0];
    const __nv_bfloat16* srcBl = &g_hbf[pp][1][nt * N_TILE][0];

    // per-thread cp.async decode: A: 8 chunks of 16B, B: 4 chunks
    // A idx in [0,2048): c8 = i&7, row = (i>>3)&127, plane = i>>10
    // B idx in [0,1024): c8 = i&7, row = (i>>3)&63,  plane = i>>9

    float d[2][4][4];
#pragma unroll
    for (int a = 0; a < 2; a++)
#pragma unroll
        for (int b = 0; b < 4; b++)
#pragma unroll
            for (int e = 0; e < 4; e++)
                d[a][b][e] = 0.0f;

    // ---- issue chunk 0 ----
    {
        const uint32_t stg = sb;
#pragma unroll
        for (int it = 0; it < 8; it++) {
            int i = tid + it * 256;
            int c8 = i & 7, row = (i >> 3) & 127, pl = i >> 10;
            const __nv_bfloat16* s = (pl ? srcAl : srcAh) + row * H + c8 * 8;
            CP_ASYNC16(stg + (pl ? OFF_AL : OFF_AH) + row * ROW_BYTES + c8 * 16, s);
        }
#pragma unroll
        for (int it = 0; it < 4; it++) {
            int i = tid + it * 256;
            int c8 = i & 7, row = (i >> 3) & 63, pl = i >> 9;
            const __nv_bfloat16* s = (pl ? srcBl : srcBh) + row * H + c8 * 8;
            CP_ASYNC16(stg + (pl ? OFF_BL : OFF_BH) + row * ROW_BYTES + c8 * 16, s);
        }
        CP_COMMIT();
    }

    // ldmatrix per-thread base offsets (within a plane)
    const uint32_t lm_a = (uint32_t)((warp_m * 32 + (lane & 15)) * ROW_BYTES + (lane >> 4) * 16);
    const uint32_t lm_b = (uint32_t)((warp_n * 32 + (lane & 15)) * ROW_BYTES + (lane >> 4) * 16);

    for (int c = 0; c < NCHUNK; c++) {
        if (c + 1 < NCHUNK) {
            const uint32_t stg = sb + ((c + 1) & 1) * STAGE_BYTES;
            const int k0 = (c + 1) * KC;
#pragma unroll
            for (int it = 0; it < 8; it++) {
                int i = tid + it * 256;
                int c8 = i & 7, row = (i >> 3) & 127, pl = i >> 10;
                const __nv_bfloat16* s = (pl ? srcAl : srcAh) + row * H + k0 + c8 * 8;
                CP_ASYNC16(stg + (pl ? OFF_AL : OFF_AH) + row * ROW_BYTES + c8 * 16, s);
            }
#pragma unroll
            for (int it = 0; it < 4; it++) {
                int i = tid + it * 256;
                int c8 = i & 7, row = (i >> 3) & 63, pl = i >> 9;
                const __nv_bfloat16* s = (pl ? srcBl : srcBh) + row * H + k0 + c8 * 8;
                CP_ASYNC16(stg + (pl ? OFF_BL : OFF_BH) + row * ROW_BYTES + c8 * 16, s);
            }
            CP_COMMIT();
            CP_WAIT(1);
        } else {
            CP_WAIT(0);
        }
        __syncthreads();

        const uint32_t stg = sb + (c & 1) * STAGE_BYTES;
#pragma unroll
        for (int k16 = 0; k16 < 4; k16++) {
            const uint32_t koff = (uint32_t)(k16 * 32);
            uint32_t af[2][2][4];   // [plane][mtile][4]
            uint32_t bfr[2][4];     // [plane][4]: {t0.b0, t1.b0, t0.b1, t1.b1}
#pragma unroll
            for (int pl = 0; pl < 2; pl++) {
                const uint32_t abase = stg + (pl ? OFF_AL : OFF_AH) + lm_a + koff;
                ldsm_x4(af[pl][0], abase);
                ldsm_x4(af[pl][1], abase + 16 * ROW_BYTES);
                const uint32_t bbase = stg + (pl ? OFF_BL : OFF_BH) + lm_b + koff;
                ldsm_x4(bfr[pl], bbase);
            }
            // combos: (Ah,Bh), (Ah,Bl), (Al,Bh)
#pragma unroll
            for (int combo = 0; combo < 3; combo++) {
                const int pa = (combo == 2) ? 1 : 0;
                const int pb = (combo == 1) ? 1 : 0;
#pragma unroll
                for (int m2 = 0; m2 < 2; m2++) {
                    // n-tiles within the x4 B load: two 8x16 frags {r0,r2} and {r1,r3}
                    mma_bf16(d[m2][0], af[pa][m2], bfr[pb][0], bfr[pb][2]);
                    mma_bf16(d[m2][1], af[pa][m2], bfr[pb][1], bfr[pb][3]);
                    // second 16-col group of the warp's 32 n-cols:
                    // reuse same B x4? No - need n+16..n+31 -> second ldmatrix
                }
            }
            // second half of warp n-tile (cols 16..31)
            uint32_t bfr2[2][4];
#pragma unroll
            for (int pl = 0; pl < 2; pl++) {
                const uint32_t bbase = stg + (pl ? OFF_BL : OFF_BH) + lm_b + koff + 16 * ROW_BYTES;
                ldsm_x4(bfr2[pl], bbase);
            }
#pragma unroll
            for (int combo = 0; combo < 3; combo++) {
                const int pa = (combo == 2) ? 1 : 0;
                const int pb = (combo == 1) ? 1 : 0;
#pragma unroll
                for (int m2 = 0; m2 < 2; m2++) {
                    mma_bf16(d[m2][2], af[pa][m2], bfr2[pb][0], bfr2[pb][2]);
                    mma_bf16(d[m2][3], af[pa][m2], bfr2[pb][1], bfr2[pb][3]);
                }
            }
        }
        __syncthreads();
    }

    // ---- store accumulators to smem epilogue tile [128][EP_STRIDE] ----
    float* ep = (float*)smem;
#pragma unroll
    for (int m2 = 0; m2 < 2; m2++) {
        const int mrow = warp_m * 32 + m2 * 16 + (lane >> 2);
#pragma unroll
        for (int n8 = 0; n8 < 4; n8++) {
            const int ncol = warp_n * 32 + n8 * 8 + (lane & 3) * 2;
            ep[mrow * EP_STRIDE + ncol]           = d[m2][n8][0];
            ep[mrow * EP_STRIDE + ncol + 1]       = d[m2][n8][1];
            ep[(mrow + 8) * EP_STRIDE + ncol]     = d[m2][n8][2];
            ep[(mrow + 8) * EP_STRIDE + ncol + 1] = d[m2][n8][3];
        }
    }
    __syncthreads();

    // ---- pointwise LSTM update ----
    // warp w handles batch cols b_local = w + 8*jj (jj 0..7), lane = il (h-row within block)
    const int il = lane;
    const int ig = mt * 32 + il;
    const int ppo = (t + 1) & 1;
    const float wxg = g_pwx[mt * 128 + 0 * 32 + il];
    const float wxi = g_pwx[mt * 128 + 1 * 32 + il];
    const float wxf = g_pwx[mt * 128 + 2 * 32 + il];
    const float wxo = g_pwx[mt * 128 + 3 * 32 + il];
#pragma unroll
    for (int jj = 0; jj < 8; jj++) {
        const int bl = wid + 8 * jj;
        const int bglob = nt * N_TILE + bl;
        const float xv = x[bglob * T + t];
        const float pg = ep[(0 * 32 + il) * EP_STRIDE + bl] + wxg * xv + bg[bglob];
        const float pi = ep[(1 * 32 + il) * EP_STRIDE + bl] + wxi * xv + bi[bglob];
        const float pf = ep[(2 * 32 + il) * EP_STRIDE + bl] + wxf * xv + bf[bglob];
        const float po = ep[(3 * 32 + il) * EP_STRIDE + bl] + wxo * xv + bo[bglob];

        const float gg = tanh_fast(pg);
        const float ii = sigm(pi);
        const float ff = sigm(pf);
        const float oo = sigm(po);

        const int idx = bglob * H + ig;
        const float cn = gg * ii + g_c[idx] * ff;
        g_c[idx] = cn;
        const float hn = tanh_fast(cn) * oo;
        g_h32[idx] = hn;
        const __nv_bfloat16 hhi = __float2bfloat16(hn);
        const float hlo = hn - __bfloat162float(hhi);
        g_hbf[ppo][0][bglob][ig] = hhi;
        g_hbf[ppo][1][bglob][ig] = __float2bfloat16(hlo);
    }
}

// ---------------- projection + softmax ----------------
__global__ void __launch_bounds__(256) proj_softmax_kernel(
    const float* __restrict__ Wph, const float* __restrict__ bp,
    float* __restrict__ out)
{
    const float* __restrict__ hT = g_h32;   // [b][i]
    const int b = threadIdx.x;

    float p[C];
#pragma unroll
    for (int c = 0; c < C; c++) p[c] = 0.0f;
    for (int k = 0; k < H; k++) {
        float hv = hT[b * H + k];
#pragma unroll
        for (int c = 0; c < C; c++)
            p[c] = fmaf(Wph[c * H + k], hv, p[c]);
    }
    float bpb = bp[b];
#pragma unroll
    for (int c = 0; c < C; c++) p[c] += bpb;

    __shared__ float red[256];
    for (int c = 0; c < C; c++) {
        red[b] = p[c];
        __syncthreads();
        for (int s = 128; s > 0; s >>= 1) {
            if (b < s) red[b] = fmaxf(red[b], red[b + s]);
            __syncthreads();
        }
        float m = red[0];
        __syncthreads();
        float e = expf(p[c] - m);
        red[b] = e;
        __syncthreads();
        for (int s = 128; s > 0; s >>= 1) {
            if (b < s) red[b] += red[b + s];
            __syncthreads();
        }
        float ssum = red[0];
        __syncthreads();
        out[b * C + c] = e / ssum;
    }
}

extern "C" void kernel_launch(void* const* d_in, const int* in_sizes, int n_in,
                              void* d_out, int out_size) {
    const float* x   = (const float*)d_in[0];
    const float* Wgx = (const float*)d_in[1];
    const float* Wgh = (const float*)d_in[2];
    const float* Wix = (const float*)d_in[3];
    const float* Wih = (const float*)d_in[4];
    const float* Wfx = (const float*)d_in[5];
    const float* Wfh = (const float*)d_in[6];
    const float* Wox = (const float*)d_in[7];
    const float* Woh = (const float*)d_in[8];
    const float* Wph = (const float*)d_in[9];
    const float* bg  = (const float*)d_in[10];
    const float* bi  = (const float*)d_in[11];
    const float* bfv = (const float*)d_in[12];
    const float* bo  = (const float*)d_in[13];
    const float* bp  = (const float*)d_in[14];
    float* out = (float*)d_out;

    cudaFuncSetAttribute(lstm_step_kernel,
                         cudaFuncAttributeMaxDynamicSharedMemorySize, SMEM_TOTAL);

    pack_w_kernel<<<4 * 1024 * 1024 / 256, 256>>>(Wgh, Wih, Wfh, Woh);
    pack_wx_kernel<<<4096 / 256, 256>>>(Wgx, Wix, Wfx, Wox);
    lstm_init_kernel<<<524288 / 256, 256>>>();

    dim3 grid(4096 / M_TILE, B / N_TILE);   // 32 x 4 = 128 CTAs
    for (int t = 0; t < T; t++) {
        lstm_step_kernel<<<grid, N_THREADS, SMEM_TOTAL>>>(x, bg, bi, bfv, bo, t);
    }
    proj_softmax_kernel<<<1, 256>>>(Wph, bp, out);
}